// round 3
// baseline (speedup 1.0000x reference)
#include <cuda_runtime.h>
#include <cstdint>

#define PERIODS 12
#define HIDDEN 32
#define MAXN 100000
#define MAXE 1600000

// Scratch (static __device__ — no allocations allowed)
__device__ float g_deg[MAXN];
__device__ float g_dinv[MAXN];
__device__ __align__(16) float g_agg[MAXN * PERIODS];

struct Params {
    float vz[HIDDEN], cz[HIDDEN], vh[HIDDEN], ch[HIDDEN], hw[HIDDEN];
    float probs[PERIODS];
    float head_b;
};
__device__ Params g_p;

// ---------------------------------------------------------------------------
// Fold the gate MLPs into per-channel (v, c) vectors + softmax(attention).
// Z = sigmoid(a*vz + cz); Ht = tanh(a*vh + ch); out = relu(sum_t p_t (1-Z)Ht) . hw + hb
// ---------------------------------------------------------------------------
__global__ void k_params(const float* __restrict__ att,
                         const float* __restrict__ czw, const float* __restrict__ czb,
                         const float* __restrict__ Lz,  const float* __restrict__ lzb,
                         const float* __restrict__ chw, const float* __restrict__ chb,
                         const float* __restrict__ Lh,  const float* __restrict__ lhb,
                         const float* __restrict__ head_w, const float* __restrict__ head_b) {
    int c = threadIdx.x;
    if (c < HIDDEN) {
        float vz = 0.f, cz = 0.f, vh = 0.f, ch = 0.f;
        #pragma unroll
        for (int j = 0; j < HIDDEN; j++) {
            vz += czw[j] * Lz[j * HIDDEN + c];
            cz += czb[j] * Lz[j * HIDDEN + c];
            vh += chw[j] * Lh[j * HIDDEN + c];
            ch += chb[j] * Lh[j * HIDDEN + c];
        }
        g_p.vz[c] = vz;
        g_p.cz[c] = cz + lzb[c];
        g_p.vh[c] = vh;
        g_p.ch[c] = ch + lhb[c];
        g_p.hw[c] = head_w[c];
    }
    if (c == 0) {
        float m = att[0];
        for (int t = 1; t < PERIODS; t++) m = fmaxf(m, att[t]);
        float e[PERIODS];
        float s = 0.f;
        for (int t = 0; t < PERIODS; t++) { e[t] = __expf(att[t] - m); s += e[t]; }
        float inv = 1.0f / s;
        for (int t = 0; t < PERIODS; t++) g_p.probs[t] = e[t] * inv;
        g_p.head_b = head_b[0];
    }
}

// deg starts at 1.0 (the added self loop with fill value 1.0)
__global__ void k_deg_init(int n) {
    int i = blockIdx.x * blockDim.x + threadIdx.x;
    if (i < n) g_deg[i] = 1.0f;
}

__global__ void k_deg_acc(const int* __restrict__ dst,
                          const float* __restrict__ ew, int e) {
    int i = blockIdx.x * blockDim.x + threadIdx.x;
    if (i < e) atomicAdd(&g_deg[dst[i]], ew[i]);
}

// dinv = deg^{-1/2}; init agg with the self-loop term dinv^2 * x[n, :]
__global__ void k_dinv_selfloop(const float4* __restrict__ x, int n) {
    int i = blockIdx.x * blockDim.x + threadIdx.x;
    if (i < n) {
        float d = g_deg[i];
        float di = rsqrtf(d > 0.f ? d : 1.0f);
        g_dinv[i] = di;
        float s = di * di;  // self loop: dinv[n] * 1.0 * dinv[n]
        float4* aggv = (float4*)g_agg;
        #pragma unroll
        for (int k = 0; k < 3; k++) {
            float4 v = x[i * 3 + k];
            v.x *= s; v.y *= s; v.z *= s; v.w *= s;
            aggv[i * 3 + k] = v;
        }
    }
}

// Per edge: agg[dst, :] += dinv[src]*ew*dinv[dst] * x[src, :]  (12 scalar REDs)
__global__ void k_edge(const int* __restrict__ src,
                       const int* __restrict__ dst,
                       const float* __restrict__ ew,
                       const float4* __restrict__ x, int e) {
    int i = blockIdx.x * blockDim.x + threadIdx.x;
    if (i < e) {
        int s = src[i];
        int d = dst[i];
        float c = g_dinv[s] * ew[i] * g_dinv[d];
        float* ap = g_agg + d * PERIODS;
        #pragma unroll
        for (int k = 0; k < 3; k++) {
            float4 v = x[s * 3 + k];
            atomicAdd(ap + k * 4 + 0, c * v.x);
            atomicAdd(ap + k * 4 + 1, c * v.y);
            atomicAdd(ap + k * 4 + 2, c * v.z);
            atomicAdd(ap + k * 4 + 3, c * v.w);
        }
    }
}

// One warp per node, lane = hidden channel. a[n,t] broadcast via shfl.
// (1-Z)*Ht = u*(1-w) / ((1+u)*(1+w)), u=exp(-(a*vz+cz)), w=exp(-2(a*vh+ch))
__global__ void k_node(float* __restrict__ out, int n) {
    int warp = (blockIdx.x * blockDim.x + threadIdx.x) >> 5;
    int lane = threadIdx.x & 31;
    if (warp >= n) return;

    float aval = (lane < PERIODS) ? g_agg[warp * PERIODS + lane] : 0.f;
    float vz = g_p.vz[lane], cz = g_p.cz[lane];
    float vh = g_p.vh[lane], ch = g_p.ch[lane];

    float hacc = 0.f;
    #pragma unroll
    for (int t = 0; t < PERIODS; t++) {
        float a  = __shfl_sync(0xffffffffu, aval, t);
        float xz = fminf(fmaxf(a * vz + cz, -20.f), 20.f);
        float xh = fminf(fmaxf(2.0f * (a * vh + ch), -40.f), 40.f);
        float u  = __expf(-xz);
        float w  = __expf(-xh);
        float num = u * (1.f - w);
        float den = (1.f + u) * (1.f + w);
        hacc += g_p.probs[t] * __fdividef(num, den);
    }
    float v = fmaxf(hacc, 0.f) * g_p.hw[lane];
    #pragma unroll
    for (int off = 16; off; off >>= 1)
        v += __shfl_xor_sync(0xffffffffu, v, off);
    if (lane == 0) out[warp] = v + g_p.head_b;
}

extern "C" void kernel_launch(void* const* d_in, const int* in_sizes, int n_in,
                              void* d_out, int out_size) {
    const float* x    = (const float*)d_in[0];
    const int*   eidx = (const int*)d_in[1];   // int32! (JAX x64 disabled)
    const float* ew   = (const float*)d_in[2];
    const float* att  = (const float*)d_in[3];
    const float* czw  = (const float*)d_in[4];
    const float* czb  = (const float*)d_in[5];
    const float* lzw  = (const float*)d_in[6];
    const float* lzb  = (const float*)d_in[7];
    // d_in[8..11]: r-gate params — provably unused (H = 0 => H*R = 0)
    const float* chw  = (const float*)d_in[12];
    const float* chb  = (const float*)d_in[13];
    const float* lhw  = (const float*)d_in[14];
    const float* lhb  = (const float*)d_in[15];
    const float* hw   = (const float*)d_in[16];
    const float* hb   = (const float*)d_in[17];
    float* out = (float*)d_out;

    int N = in_sizes[0] / PERIODS;
    int E = in_sizes[2];
    const int* src = eidx;
    const int* dst = eidx + E;

    k_params<<<1, 32>>>(att, czw, czb, lzw, lzb, chw, chb, lhw, lhb, hw, hb);
    k_deg_init<<<(N + 255) / 256, 256>>>(N);
    k_deg_acc<<<(E + 255) / 256, 256>>>(dst, ew, E);
    k_dinv_selfloop<<<(N + 255) / 256, 256>>>((const float4*)x, N);
    k_edge<<<(E + 255) / 256, 256>>>(src, dst, ew, (const float4*)x, E);
    k_node<<<(N * 32 + 127) / 128, 128>>>(out, N);
}

// round 4
// speedup vs baseline: 1.9094x; 1.9094x over previous
#include <cuda_runtime.h>
#include <cstdint>

#define PERIODS 12
#define HIDDEN 32
#define MAXN 100000
#define MAXE 1600000

// Scratch (static __device__ — no allocations allowed)
__device__ float g_deg[MAXN];
__device__ float g_dinv[MAXN];
__device__ __align__(16) float g_agg[MAXN * PERIODS];

struct Params {
    float vz[HIDDEN], cz[HIDDEN], vh[HIDDEN], ch[HIDDEN], hw[HIDDEN];
    float probs[PERIODS];
    float head_b;
};
__device__ Params g_p;

__device__ __forceinline__ float tanhx(float x) {
    float y;
    asm("tanh.approx.f32 %0, %1;" : "=f"(y) : "f"(x));
    return y;
}

// ---------------------------------------------------------------------------
// Fold the gate MLPs into per-channel (v, c) vectors + softmax(attention).
// Z = sigmoid(a*vz + cz); Ht = tanh(a*vh + ch); out = relu(sum_t p_t (1-Z)Ht) . hw + hb
// ---------------------------------------------------------------------------
__global__ void k_params(const float* __restrict__ att,
                         const float* __restrict__ czw, const float* __restrict__ czb,
                         const float* __restrict__ Lz,  const float* __restrict__ lzb,
                         const float* __restrict__ chw, const float* __restrict__ chb,
                         const float* __restrict__ Lh,  const float* __restrict__ lhb,
                         const float* __restrict__ head_w, const float* __restrict__ head_b) {
    int c = threadIdx.x;
    if (c < HIDDEN) {
        float vz = 0.f, cz = 0.f, vh = 0.f, ch = 0.f;
        #pragma unroll
        for (int j = 0; j < HIDDEN; j++) {
            vz += czw[j] * Lz[j * HIDDEN + c];
            cz += czb[j] * Lz[j * HIDDEN + c];
            vh += chw[j] * Lh[j * HIDDEN + c];
            ch += chb[j] * Lh[j * HIDDEN + c];
        }
        g_p.vz[c] = vz;
        g_p.cz[c] = cz + lzb[c];
        g_p.vh[c] = vh;
        g_p.ch[c] = ch + lhb[c];
        g_p.hw[c] = head_w[c];
    }
    if (c == 0) {
        float m = att[0];
        for (int t = 1; t < PERIODS; t++) m = fmaxf(m, att[t]);
        float e[PERIODS];
        float s = 0.f;
        for (int t = 0; t < PERIODS; t++) { e[t] = __expf(att[t] - m); s += e[t]; }
        float inv = 1.0f / s;
        for (int t = 0; t < PERIODS; t++) g_p.probs[t] = e[t] * inv;
        g_p.head_b = head_b[0];
    }
}

// deg starts at 1.0 (the added self loop with fill value 1.0)
__global__ void k_deg_init(int n) {
    int i = blockIdx.x * blockDim.x + threadIdx.x;
    if (i < n) g_deg[i] = 1.0f;
}

__global__ void k_deg_acc(const int* __restrict__ dst,
                          const float* __restrict__ ew, int e) {
    int i = blockIdx.x * blockDim.x + threadIdx.x;
    if (i < e) atomicAdd(&g_deg[dst[i]], ew[i]);
}

// dinv = deg^{-1/2}; init agg with the self-loop term dinv^2 * x[n, :]
__global__ void k_dinv_selfloop(const float4* __restrict__ x, int n) {
    int i = blockIdx.x * blockDim.x + threadIdx.x;
    if (i < n) {
        float d = g_deg[i];
        float di = rsqrtf(d > 0.f ? d : 1.0f);
        g_dinv[i] = di;
        float s = di * di;  // self loop: dinv[n] * 1.0 * dinv[n]
        float4* aggv = (float4*)g_agg;
        #pragma unroll
        for (int k = 0; k < 3; k++) {
            float4 v = x[i * 3 + k];
            v.x *= s; v.y *= s; v.z *= s; v.w *= s;
            aggv[i * 3 + k] = v;
        }
    }
}

// Per edge: agg[dst, :] += dinv[src]*ew*dinv[dst] * x[src, :]  (3x red.v4)
__global__ void k_edge(const int* __restrict__ src,
                       const int* __restrict__ dst,
                       const float* __restrict__ ew,
                       const float4* __restrict__ x, int e) {
    int i = blockIdx.x * blockDim.x + threadIdx.x;
    if (i < e) {
        int s = src[i];
        int d = dst[i];
        float c = g_dinv[s] * ew[i] * g_dinv[d];
        float* ap = g_agg + d * PERIODS;
        #pragma unroll
        for (int k = 0; k < 3; k++) {
            float4 v = x[s * 3 + k];
            asm volatile("red.global.add.v4.f32 [%0], {%1,%2,%3,%4};"
                         :: "l"(ap + k * 4),
                            "f"(c * v.x), "f"(c * v.y), "f"(c * v.z), "f"(c * v.w)
                         : "memory");
        }
    }
}

// One warp per node, lane = hidden channel. a[n,t] broadcast via shfl.
// (1-Z)*Ht = (0.5 - 0.5*tanh(xz/2)) * tanh(xh)   [2 MUFU per period]
__global__ void k_node(float* __restrict__ out, int n) {
    int warp = (blockIdx.x * blockDim.x + threadIdx.x) >> 5;
    int lane = threadIdx.x & 31;
    if (warp >= n) return;

    float aval = (lane < PERIODS) ? g_agg[warp * PERIODS + lane] : 0.f;
    float vz = g_p.vz[lane] * 0.5f, cz = g_p.cz[lane] * 0.5f;
    float vh = g_p.vh[lane],        ch = g_p.ch[lane];

    float hacc = 0.f;
    #pragma unroll
    for (int t = 0; t < PERIODS; t++) {
        float a  = __shfl_sync(0xffffffffu, aval, t);
        float tz = tanhx(a * vz + cz);        // tanh(xz/2)
        float th = tanhx(a * vh + ch);        // tanh(xh)
        hacc += g_p.probs[t] * (0.5f - 0.5f * tz) * th;
    }
    float v = fmaxf(hacc, 0.f) * g_p.hw[lane];
    #pragma unroll
    for (int off = 16; off; off >>= 1)
        v += __shfl_xor_sync(0xffffffffu, v, off);
    if (lane == 0) out[warp] = v + g_p.head_b;
}

extern "C" void kernel_launch(void* const* d_in, const int* in_sizes, int n_in,
                              void* d_out, int out_size) {
    const float* x    = (const float*)d_in[0];
    const int*   eidx = (const int*)d_in[1];   // int32 (JAX x64 disabled)
    const float* ew   = (const float*)d_in[2];
    const float* att  = (const float*)d_in[3];
    const float* czw  = (const float*)d_in[4];
    const float* czb  = (const float*)d_in[5];
    const float* lzw  = (const float*)d_in[6];
    const float* lzb  = (const float*)d_in[7];
    // d_in[8..11]: r-gate params — provably unused (H = 0 => H*R = 0)
    const float* chw  = (const float*)d_in[12];
    const float* chb  = (const float*)d_in[13];
    const float* lhw  = (const float*)d_in[14];
    const float* lhb  = (const float*)d_in[15];
    const float* hw   = (const float*)d_in[16];
    const float* hb   = (const float*)d_in[17];
    float* out = (float*)d_out;

    int N = in_sizes[0] / PERIODS;
    int E = in_sizes[2];
    const int* src = eidx;
    const int* dst = eidx + E;

    k_params<<<1, 32>>>(att, czw, czb, lzw, lzb, chw, chb, lhw, lhb, hw, hb);
    k_deg_init<<<(N + 255) / 256, 256>>>(N);
    k_deg_acc<<<(E + 255) / 256, 256>>>(dst, ew, E);
    k_dinv_selfloop<<<(N + 255) / 256, 256>>>((const float4*)x, N);
    k_edge<<<(E + 255) / 256, 256>>>(src, dst, ew, (const float4*)x, E);
    k_node<<<(N * 32 + 127) / 128, 128>>>(out, N);
}

// round 5
// speedup vs baseline: 1.9101x; 1.0004x over previous
#include <cuda_runtime.h>
#include <cstdint>

#define PERIODS 12
#define ROWPAD 16          // agg/xs rows padded to 64B (sector-aligned)
#define HIDDEN 32
#define MAXN 100000
#define MAXE 1600000

// Scratch (static __device__ — no allocations allowed)
__device__ float g_deg[MAXN];
__device__ float g_dinv[MAXN];
__device__ __align__(16) float g_agg[MAXN * ROWPAD];  // 6.4MB
__device__ __align__(16) float g_xs[MAXN * ROWPAD];   // 6.4MB  xs = dinv[n]*x[n,:]

struct Params {
    float vz[HIDDEN], cz[HIDDEN], vh[HIDDEN], ch[HIDDEN], hw[HIDDEN];
    float probs[PERIODS];
    float head_b;
};
__device__ Params g_p;

__device__ __forceinline__ float tanhx(float x) {
    float y;
    asm("tanh.approx.f32 %0, %1;" : "=f"(y) : "f"(x));
    return y;
}

// ---------------------------------------------------------------------------
// Grid-wide: deg[i] = 1.0 (self loop, fill value 1.0).
// Block 0 additionally folds the gate MLPs into per-channel (v, c) vectors
// and softmaxes the attention.
// Z = sigmoid(a*vz + cz); Ht = tanh(a*vh + ch); out = relu(sum_t p_t (1-Z)Ht) . hw + hb
// ---------------------------------------------------------------------------
__global__ void k_params_deginit(int n,
                         const float* __restrict__ att,
                         const float* __restrict__ czw, const float* __restrict__ czb,
                         const float* __restrict__ Lz,  const float* __restrict__ lzb,
                         const float* __restrict__ chw, const float* __restrict__ chb,
                         const float* __restrict__ Lh,  const float* __restrict__ lhb,
                         const float* __restrict__ head_w, const float* __restrict__ head_b) {
    int i = blockIdx.x * blockDim.x + threadIdx.x;
    if (i < n) g_deg[i] = 1.0f;

    if (blockIdx.x == 0) {
        int c = threadIdx.x;
        if (c < HIDDEN) {
            float vz = 0.f, cz = 0.f, vh = 0.f, ch = 0.f;
            #pragma unroll
            for (int j = 0; j < HIDDEN; j++) {
                vz += czw[j] * Lz[j * HIDDEN + c];
                cz += czb[j] * Lz[j * HIDDEN + c];
                vh += chw[j] * Lh[j * HIDDEN + c];
                ch += chb[j] * Lh[j * HIDDEN + c];
            }
            g_p.vz[c] = vz;
            g_p.cz[c] = cz + lzb[c];
            g_p.vh[c] = vh;
            g_p.ch[c] = ch + lhb[c];
            g_p.hw[c] = head_w[c];
        }
        if (c == 0) {
            float m = att[0];
            for (int t = 1; t < PERIODS; t++) m = fmaxf(m, att[t]);
            float e[PERIODS];
            float s = 0.f;
            for (int t = 0; t < PERIODS; t++) { e[t] = __expf(att[t] - m); s += e[t]; }
            float inv = 1.0f / s;
            for (int t = 0; t < PERIODS; t++) g_p.probs[t] = e[t] * inv;
            g_p.head_b = head_b[0];
        }
    }
}

__global__ void k_deg_acc(const int* __restrict__ dst,
                          const float* __restrict__ ew, int e) {
    int i = blockIdx.x * blockDim.x + threadIdx.x;
    if (i < e) atomicAdd(&g_deg[dst[i]], ew[i]);
}

// dinv = deg^{-1/2};  xs = dinv*x (padded row);  agg init = dinv*xs = dinv^2*x
__global__ void k_dinv_selfloop(const float4* __restrict__ x, int n) {
    int i = blockIdx.x * blockDim.x + threadIdx.x;
    if (i < n) {
        float d = g_deg[i];
        float di = rsqrtf(d > 0.f ? d : 1.0f);
        g_dinv[i] = di;
        float4* xsv  = (float4*)g_xs;
        float4* aggv = (float4*)g_agg;
        #pragma unroll
        for (int k = 0; k < 3; k++) {
            float4 v = x[i * 3 + k];                 // x rows are tight (12 floats)
            float4 s; s.x = di * v.x; s.y = di * v.y; s.z = di * v.z; s.w = di * v.w;
            xsv[i * 4 + k] = s;                      // padded row (16 floats)
            float4 a; a.x = di * s.x; a.y = di * s.y; a.z = di * s.z; a.w = di * s.w;
            aggv[i * 4 + k] = a;
        }
    }
}

// Per edge: agg[dst,:] += (ew * dinv[dst]) * xs[src,:]   (3x red.v4)
__global__ void k_edge(const int* __restrict__ src,
                       const int* __restrict__ dst,
                       const float* __restrict__ ew,
                       int e) {
    int i = blockIdx.x * blockDim.x + threadIdx.x;
    if (i < e) {
        int s = src[i];
        int d = dst[i];
        float c = ew[i] * g_dinv[d];
        const float4* xsv = (const float4*)g_xs;
        float* ap = g_agg + d * ROWPAD;
        #pragma unroll
        for (int k = 0; k < 3; k++) {
            float4 v = xsv[s * 4 + k];
            asm volatile("red.global.add.v4.f32 [%0], {%1,%2,%3,%4};"
                         :: "l"(ap + k * 4),
                            "f"(c * v.x), "f"(c * v.y), "f"(c * v.z), "f"(c * v.w)
                         : "memory");
        }
    }
}

// One warp per node, lane = hidden channel. a[n,t] broadcast via shfl.
// (1-Z)*Ht = (0.5 - 0.5*tanh(xz/2)) * tanh(xh)   [2 MUFU per period]
__global__ void k_node(float* __restrict__ out, int n) {
    int warp = (blockIdx.x * blockDim.x + threadIdx.x) >> 5;
    int lane = threadIdx.x & 31;
    if (warp >= n) return;

    float aval = (lane < PERIODS) ? g_agg[warp * ROWPAD + lane] : 0.f;
    float vz = g_p.vz[lane] * 0.5f, cz = g_p.cz[lane] * 0.5f;
    float vh = g_p.vh[lane],        ch = g_p.ch[lane];

    float hacc = 0.f;
    #pragma unroll
    for (int t = 0; t < PERIODS; t++) {
        float a  = __shfl_sync(0xffffffffu, aval, t);
        float tz = tanhx(a * vz + cz);        // tanh(xz/2)
        float th = tanhx(a * vh + ch);        // tanh(xh)
        hacc += g_p.probs[t] * (0.5f - 0.5f * tz) * th;
    }
    float v = fmaxf(hacc, 0.f) * g_p.hw[lane];
    #pragma unroll
    for (int off = 16; off; off >>= 1)
        v += __shfl_xor_sync(0xffffffffu, v, off);
    if (lane == 0) out[warp] = v + g_p.head_b;
}

extern "C" void kernel_launch(void* const* d_in, const int* in_sizes, int n_in,
                              void* d_out, int out_size) {
    const float* x    = (const float*)d_in[0];
    const int*   eidx = (const int*)d_in[1];   // int32 (JAX x64 disabled)
    const float* ew   = (const float*)d_in[2];
    const float* att  = (const float*)d_in[3];
    const float* czw  = (const float*)d_in[4];
    const float* czb  = (const float*)d_in[5];
    const float* lzw  = (const float*)d_in[6];
    const float* lzb  = (const float*)d_in[7];
    // d_in[8..11]: r-gate params — provably unused (H = 0 => H*R = 0)
    const float* chw  = (const float*)d_in[12];
    const float* chb  = (const float*)d_in[13];
    const float* lhw  = (const float*)d_in[14];
    const float* lhb  = (const float*)d_in[15];
    const float* hw   = (const float*)d_in[16];
    const float* hb   = (const float*)d_in[17];
    float* out = (float*)d_out;

    int N = in_sizes[0] / PERIODS;
    int E = in_sizes[2];
    const int* src = eidx;
    const int* dst = eidx + E;

    k_params_deginit<<<(N + 255) / 256, 256>>>(N, att, czw, czb, lzw, lzb,
                                               chw, chb, lhw, lhb, hw, hb);
    k_deg_acc<<<(E + 255) / 256, 256>>>(dst, ew, E);
    k_dinv_selfloop<<<(N + 255) / 256, 256>>>((const float4*)x, N);
    k_edge<<<(E + 255) / 256, 256>>>(src, dst, ew, E);
    k_node<<<(N * 32 + 127) / 128, 128>>>(out, N);
}

// round 6
// speedup vs baseline: 2.3338x; 1.2218x over previous
#include <cuda_runtime.h>
#include <cuda_fp16.h>
#include <cstdint>

#define PERIODS 12
#define ROWPAD 16          // agg rows: 16 floats = 64B; xs rows: 16 halves = 32B
#define HIDDEN 32
#define MAXN 100000
#define MAXE 1600000

// Scratch (static __device__ — no allocations allowed)
__device__ float g_deg[MAXN];
__device__ float g_dinv[MAXN];
__device__ __align__(16) float g_agg[MAXN * ROWPAD];      // 6.4MB, agg' (pre-dinv[dst])
__device__ __align__(32) __half g_xsh[MAXN * ROWPAD];     // 3.2MB, xs = dinv*x in fp16

struct Params {
    float vz[HIDDEN], cz[HIDDEN], vh[HIDDEN], ch[HIDDEN], hw[HIDDEN];
    float probs[PERIODS];
    float head_b;
};
__device__ Params g_p;

__device__ __forceinline__ float tanhx(float x) {
    float y;
    asm("tanh.approx.f32 %0, %1;" : "=f"(y) : "f"(x));
    return y;
}

// ---------------------------------------------------------------------------
// Grid-wide: deg[i] = 1.0 (self loop, fill value 1.0).
// Block 0 folds the gate MLPs into per-channel (v, c) vectors + softmax(att).
// ---------------------------------------------------------------------------
__global__ void k_params_deginit(int n,
                         const float* __restrict__ att,
                         const float* __restrict__ czw, const float* __restrict__ czb,
                         const float* __restrict__ Lz,  const float* __restrict__ lzb,
                         const float* __restrict__ chw, const float* __restrict__ chb,
                         const float* __restrict__ Lh,  const float* __restrict__ lhb,
                         const float* __restrict__ head_w, const float* __restrict__ head_b) {
    int i = blockIdx.x * blockDim.x + threadIdx.x;
    if (i < n) g_deg[i] = 1.0f;

    if (blockIdx.x == 0) {
        int c = threadIdx.x;
        if (c < HIDDEN) {
            float vz = 0.f, cz = 0.f, vh = 0.f, ch = 0.f;
            #pragma unroll
            for (int j = 0; j < HIDDEN; j++) {
                vz += czw[j] * Lz[j * HIDDEN + c];
                cz += czb[j] * Lz[j * HIDDEN + c];
                vh += chw[j] * Lh[j * HIDDEN + c];
                ch += chb[j] * Lh[j * HIDDEN + c];
            }
            g_p.vz[c] = vz;
            g_p.cz[c] = cz + lzb[c];
            g_p.vh[c] = vh;
            g_p.ch[c] = ch + lhb[c];
            g_p.hw[c] = head_w[c];
        }
        if (c == 0) {
            float m = att[0];
            for (int t = 1; t < PERIODS; t++) m = fmaxf(m, att[t]);
            float e[PERIODS];
            float s = 0.f;
            for (int t = 0; t < PERIODS; t++) { e[t] = __expf(att[t] - m); s += e[t]; }
            float inv = 1.0f / s;
            for (int t = 0; t < PERIODS; t++) g_p.probs[t] = e[t] * inv;
            g_p.head_b = head_b[0];
        }
    }
}

__global__ void k_deg_acc(const int* __restrict__ dst,
                          const float* __restrict__ ew, int e) {
    int i = blockIdx.x * blockDim.x + threadIdx.x;
    if (i < e) atomicAdd(&g_deg[dst[i]], ew[i]);
}

// dinv = deg^{-1/2};  xs_h = fp16(dinv*x) for edge gathers;
// agg' init = f32 dinv*x (exact self-loop; k_node multiplies by dinv[n] later)
__global__ void k_dinv_xs(const float4* __restrict__ x, int n) {
    int i = blockIdx.x * blockDim.x + threadIdx.x;
    if (i < n) {
        float d = g_deg[i];
        float di = rsqrtf(d > 0.f ? d : 1.0f);
        g_dinv[i] = di;
        float4* aggv = (float4*)g_agg;
        __half2* xshv = (__half2*)(g_xsh + i * ROWPAD);
        #pragma unroll
        for (int k = 0; k < 3; k++) {
            float4 v = x[i * 3 + k];                 // x rows tight (12 floats)
            float4 s; s.x = di * v.x; s.y = di * v.y; s.z = di * v.z; s.w = di * v.w;
            aggv[i * 4 + k] = s;                     // f32 exact init (= xs)
            xshv[k * 2 + 0] = __floats2half2_rn(s.x, s.y);
            xshv[k * 2 + 1] = __floats2half2_rn(s.z, s.w);
        }
    }
}

// Per edge: agg'[dst,:] += ew * xs_h[src,:]   (1x 32B gather + 3x red.v4)
__global__ void k_edge(const int* __restrict__ src,
                       const int* __restrict__ dst,
                       const float* __restrict__ ew,
                       int e) {
    int i = blockIdx.x * blockDim.x + threadIdx.x;
    if (i < e) {
        int s = src[i];
        int d = dst[i];
        float c = ew[i];
        const uint4* xp = (const uint4*)(g_xsh + s * ROWPAD);
        uint4 q0 = xp[0];                       // halves 0..7
        uint2 q1 = ((const uint2*)xp)[2];       // halves 8..11
        float* ap = g_agg + d * ROWPAD;

        float2 f0 = __half22float2(*(__half2*)&q0.x);
        float2 f1 = __half22float2(*(__half2*)&q0.y);
        asm volatile("red.global.add.v4.f32 [%0], {%1,%2,%3,%4};"
                     :: "l"(ap), "f"(c * f0.x), "f"(c * f0.y),
                        "f"(c * f1.x), "f"(c * f1.y) : "memory");
        float2 f2 = __half22float2(*(__half2*)&q0.z);
        float2 f3 = __half22float2(*(__half2*)&q0.w);
        asm volatile("red.global.add.v4.f32 [%0], {%1,%2,%3,%4};"
                     :: "l"(ap + 4), "f"(c * f2.x), "f"(c * f2.y),
                        "f"(c * f3.x), "f"(c * f3.y) : "memory");
        float2 f4 = __half22float2(*(__half2*)&q1.x);
        float2 f5 = __half22float2(*(__half2*)&q1.y);
        asm volatile("red.global.add.v4.f32 [%0], {%1,%2,%3,%4};"
                     :: "l"(ap + 8), "f"(c * f4.x), "f"(c * f4.y),
                        "f"(c * f5.x), "f"(c * f5.y) : "memory");
    }
}

// One warp per node, lane = hidden channel. a[n,t] = dinv[n]*agg'[n,t], shfl-broadcast.
// (1-Z)*Ht = (0.5 - 0.5*tanh(xz/2)) * tanh(xh)   [2 MUFU per period]
__global__ void k_node(float* __restrict__ out, int n) {
    int warp = (blockIdx.x * blockDim.x + threadIdx.x) >> 5;
    int lane = threadIdx.x & 31;
    if (warp >= n) return;

    float di = g_dinv[warp];   // broadcast load
    float aval = (lane < PERIODS) ? di * g_agg[warp * ROWPAD + lane] : 0.f;
    float vz = g_p.vz[lane] * 0.5f, cz = g_p.cz[lane] * 0.5f;
    float vh = g_p.vh[lane],        ch = g_p.ch[lane];

    float hacc = 0.f;
    #pragma unroll
    for (int t = 0; t < PERIODS; t++) {
        float a  = __shfl_sync(0xffffffffu, aval, t);
        float tz = tanhx(a * vz + cz);        // tanh(xz/2)
        float th = tanhx(a * vh + ch);        // tanh(xh)
        hacc += g_p.probs[t] * (0.5f - 0.5f * tz) * th;
    }
    float v = fmaxf(hacc, 0.f) * g_p.hw[lane];
    #pragma unroll
    for (int off = 16; off; off >>= 1)
        v += __shfl_xor_sync(0xffffffffu, v, off);
    if (lane == 0) out[warp] = v + g_p.head_b;
}

extern "C" void kernel_launch(void* const* d_in, const int* in_sizes, int n_in,
                              void* d_out, int out_size) {
    const float* x    = (const float*)d_in[0];
    const int*   eidx = (const int*)d_in[1];   // int32 (JAX x64 disabled)
    const float* ew   = (const float*)d_in[2];
    const float* att  = (const float*)d_in[3];
    const float* czw  = (const float*)d_in[4];
    const float* czb  = (const float*)d_in[5];
    const float* lzw  = (const float*)d_in[6];
    const float* lzb  = (const float*)d_in[7];
    // d_in[8..11]: r-gate params — provably unused (H = 0 => H*R = 0)
    const float* chw  = (const float*)d_in[12];
    const float* chb  = (const float*)d_in[13];
    const float* lhw  = (const float*)d_in[14];
    const float* lhb  = (const float*)d_in[15];
    const float* hw   = (const float*)d_in[16];
    const float* hb   = (const float*)d_in[17];
    float* out = (float*)d_out;

    int N = in_sizes[0] / PERIODS;
    int E = in_sizes[2];
    const int* src = eidx;
    const int* dst = eidx + E;

    k_params_deginit<<<(N + 255) / 256, 256>>>(N, att, czw, czb, lzw, lzb,
                                               chw, chb, lhw, lhb, hw, hb);
    k_deg_acc<<<(E + 255) / 256, 256>>>(dst, ew, E);
    k_dinv_xs<<<(N + 255) / 256, 256>>>((const float4*)x, N);
    k_edge<<<(E + 255) / 256, 256>>>(src, dst, ew, E);
    k_node<<<(N * 32 + 127) / 128, 128>>>(out, N);
}

// round 7
// speedup vs baseline: 2.6242x; 1.1245x over previous
#include <cuda_runtime.h>
#include <cuda_fp16.h>
#include <cstdint>

#define PERIODS 12
#define ROWPAD 16          // xs/agg rows: 16 halves = 32B (1 sector)
#define HIDDEN 32
#define MAXN 100000
#define MAXE 1600000

// Scratch (static __device__ — no allocations allowed)
__device__ float g_deg[MAXN];
__device__ float g_dinv[MAXN];
__device__ __align__(32) __half g_aggh[MAXN * ROWPAD];    // 3.2MB fp16 edge-accumulator
__device__ __align__(32) __half g_xsh[MAXN * ROWPAD];     // 3.2MB xs = dinv*x in fp16

struct Params {
    float vz[HIDDEN], cz[HIDDEN], vh[HIDDEN], ch[HIDDEN], hw[HIDDEN];
    float probs[PERIODS];
    float head_b;
};
__device__ Params g_p;

__device__ __forceinline__ float tanhx(float x) {
    float y;
    asm("tanh.approx.f32 %0, %1;" : "=f"(y) : "f"(x));
    return y;
}

// ---------------------------------------------------------------------------
// Grid-wide: deg[i] = 1.0 (self loop) and agg[i,:] = 0.
// Block 0 folds the gate MLPs into per-channel (v, c) vectors + softmax(att).
// ---------------------------------------------------------------------------
__global__ void k_params_deginit(int n,
                         const float* __restrict__ att,
                         const float* __restrict__ czw, const float* __restrict__ czb,
                         const float* __restrict__ Lz,  const float* __restrict__ lzb,
                         const float* __restrict__ chw, const float* __restrict__ chb,
                         const float* __restrict__ Lh,  const float* __restrict__ lhb,
                         const float* __restrict__ head_w, const float* __restrict__ head_b) {
    int i = blockIdx.x * blockDim.x + threadIdx.x;
    if (i < n) {
        g_deg[i] = 1.0f;
        uint4 z = {0u, 0u, 0u, 0u};
        uint4* ag = (uint4*)g_aggh;
        ag[i * 2 + 0] = z;   // halves 0..7
        ag[i * 2 + 1] = z;   // halves 8..15
    }

    if (blockIdx.x == 0) {
        int c = threadIdx.x;
        if (c < HIDDEN) {
            float vz = 0.f, cz = 0.f, vh = 0.f, ch = 0.f;
            #pragma unroll
            for (int j = 0; j < HIDDEN; j++) {
                vz += czw[j] * Lz[j * HIDDEN + c];
                cz += czb[j] * Lz[j * HIDDEN + c];
                vh += chw[j] * Lh[j * HIDDEN + c];
                ch += chb[j] * Lh[j * HIDDEN + c];
            }
            g_p.vz[c] = vz;
            g_p.cz[c] = cz + lzb[c];
            g_p.vh[c] = vh;
            g_p.ch[c] = ch + lhb[c];
            g_p.hw[c] = head_w[c];
        }
        if (c == 0) {
            float m = att[0];
            for (int t = 1; t < PERIODS; t++) m = fmaxf(m, att[t]);
            float e[PERIODS];
            float s = 0.f;
            for (int t = 0; t < PERIODS; t++) { e[t] = __expf(att[t] - m); s += e[t]; }
            float inv = 1.0f / s;
            for (int t = 0; t < PERIODS; t++) g_p.probs[t] = e[t] * inv;
            g_p.head_b = head_b[0];
        }
    }
}

__global__ void k_deg_acc(const int* __restrict__ dst,
                          const float* __restrict__ ew, int e) {
    int i = blockIdx.x * blockDim.x + threadIdx.x;
    if (i < e) atomicAdd(&g_deg[dst[i]], ew[i]);
}

// dinv = deg^{-1/2};  xs_h = fp16(dinv*x) for edge gathers.
__global__ void k_dinv_xs(const float4* __restrict__ x, int n) {
    int i = blockIdx.x * blockDim.x + threadIdx.x;
    if (i < n) {
        float d = g_deg[i];
        float di = rsqrtf(d > 0.f ? d : 1.0f);
        g_dinv[i] = di;
        __half2* xshv = (__half2*)(g_xsh + i * ROWPAD);
        #pragma unroll
        for (int k = 0; k < 3; k++) {
            float4 v = x[i * 3 + k];                 // x rows tight (12 floats)
            xshv[k * 2 + 0] = __floats2half2_rn(di * v.x, di * v.y);
            xshv[k * 2 + 1] = __floats2half2_rn(di * v.z, di * v.w);
        }
    }
}

// Per edge: agg[dst,:] += ew * xs_h[src,:]  — fp16: 1x 32B gather + v4.f16x2 + v2.f16x2
__global__ void k_edge(const int* __restrict__ src,
                       const int* __restrict__ dst,
                       const float* __restrict__ ew,
                       int e) {
    int i = blockIdx.x * blockDim.x + threadIdx.x;
    if (i < e) {
        int s = src[i];
        int d = dst[i];
        __half2 c2 = __half2half2(__float2half_rn(ew[i]));
        const uint4* xp = (const uint4*)(g_xsh + s * ROWPAD);
        uint4 q0 = xp[0];                       // halves 0..7
        uint2 q1 = ((const uint2*)xp)[2];       // halves 8..11
        __half* ap = g_aggh + d * ROWPAD;

        __half2 p0 = __hmul2(*(__half2*)&q0.x, c2);
        __half2 p1 = __hmul2(*(__half2*)&q0.y, c2);
        __half2 p2 = __hmul2(*(__half2*)&q0.z, c2);
        __half2 p3 = __hmul2(*(__half2*)&q0.w, c2);
        __half2 p4 = __hmul2(*(__half2*)&q1.x, c2);
        __half2 p5 = __hmul2(*(__half2*)&q1.y, c2);

        asm volatile("red.global.add.noftz.v4.f16x2 [%0], {%1,%2,%3,%4};"
                     :: "l"(ap),
                        "r"(*(unsigned*)&p0), "r"(*(unsigned*)&p1),
                        "r"(*(unsigned*)&p2), "r"(*(unsigned*)&p3) : "memory");
        asm volatile("red.global.add.noftz.v2.f16x2 [%0], {%1,%2};"
                     :: "l"(ap + 8),
                        "r"(*(unsigned*)&p4), "r"(*(unsigned*)&p5) : "memory");
    }
}

// One warp per node, lane = period for the load; lane = channel for the math.
// a[n,t] = dinv*(agg_fp16[n,t] + dinv*x[n,t])   (self term exact f32)
// (1-Z)*Ht = (0.5 - 0.5*tanh(xz/2)) * tanh(xh)   [2 MUFU per period]
__global__ void k_node(const float* __restrict__ x, float* __restrict__ out, int n) {
    int warp = (blockIdx.x * blockDim.x + threadIdx.x) >> 5;
    int lane = threadIdx.x & 31;
    if (warp >= n) return;

    float di = g_dinv[warp];   // broadcast load
    float aval = 0.f;
    if (lane < PERIODS) {
        float edge = __half2float(g_aggh[warp * ROWPAD + lane]);
        aval = di * (edge + di * x[warp * PERIODS + lane]);
    }
    float vz = g_p.vz[lane] * 0.5f, cz = g_p.cz[lane] * 0.5f;
    float vh = g_p.vh[lane],        ch = g_p.ch[lane];

    float hacc = 0.f;
    #pragma unroll
    for (int t = 0; t < PERIODS; t++) {
        float a  = __shfl_sync(0xffffffffu, aval, t);
        float tz = tanhx(a * vz + cz);        // tanh(xz/2)
        float th = tanhx(a * vh + ch);        // tanh(xh)
        hacc += g_p.probs[t] * (0.5f - 0.5f * tz) * th;
    }
    float v = fmaxf(hacc, 0.f) * g_p.hw[lane];
    #pragma unroll
    for (int off = 16; off; off >>= 1)
        v += __shfl_xor_sync(0xffffffffu, v, off);
    if (lane == 0) out[warp] = v + g_p.head_b;
}

extern "C" void kernel_launch(void* const* d_in, const int* in_sizes, int n_in,
                              void* d_out, int out_size) {
    const float* x    = (const float*)d_in[0];
    const int*   eidx = (const int*)d_in[1];   // int32 (JAX x64 disabled)
    const float* ew   = (const float*)d_in[2];
    const float* att  = (const float*)d_in[3];
    const float* czw  = (const float*)d_in[4];
    const float* czb  = (const float*)d_in[5];
    const float* lzw  = (const float*)d_in[6];
    const float* lzb  = (const float*)d_in[7];
    // d_in[8..11]: r-gate params — provably unused (H = 0 => H*R = 0)
    const float* chw  = (const float*)d_in[12];
    const float* chb  = (const float*)d_in[13];
    const float* lhw  = (const float*)d_in[14];
    const float* lhb  = (const float*)d_in[15];
    const float* hw   = (const float*)d_in[16];
    const float* hb   = (const float*)d_in[17];
    float* out = (float*)d_out;

    int N = in_sizes[0] / PERIODS;
    int E = in_sizes[2];
    const int* src = eidx;
    const int* dst = eidx + E;

    k_params_deginit<<<(N + 255) / 256, 256>>>(N, att, czw, czb, lzw, lzb,
                                               chw, chb, lhw, lhb, hw, hb);
    k_deg_acc<<<(E + 255) / 256, 256>>>(dst, ew, E);
    k_dinv_xs<<<(N + 255) / 256, 256>>>((const float4*)x, N);
    k_edge<<<(E + 255) / 256, 256>>>(src, dst, ew, E);
    k_node<<<(N * 32 + 127) / 128, 128>>>(x, out, N);
}